// round 9
// baseline (speedup 1.0000x reference)
#include <cuda_runtime.h>

#define NN 50000
#define EE 800000
#define FF 256
#define FF4 64

// ---------------- device scratch (static: no cudaMalloc allowed) ----------------
__device__ float g_T0[NN * FF];
__device__ float g_T1[NN * FF];
__device__ float g_Q1buf[NN * FF];
__device__ int   g_cnt[NN];
__device__ int   g_rowptr[NN + 1];
__device__ int   g_cursor[NN];
__device__ int   g_csrsrc[EE];
__device__ float g_d1[NN];
__device__ float g_d2[NN];
__device__ float g_S[FF * FF];
__device__ float g_W23[FF * FF];
__device__ float g_Wt[FF * FF];
__device__ float g_Tm[FF * FF];
__device__ float g_R[FF * FF];
__device__ float g_sum[FF], g_sumsq[FF], g_bns[FF], g_bnt[FF];
__device__ float g_a1[FF], g_c1[FF], g_a2[FF], g_c2[FF];
__device__ float g_u[FF], g_v1[FF], g_w1[FF], g_v2[FF], g_w2[FF];
__device__ float g_scal[4];

// ---------------- helpers ----------------
__device__ __forceinline__ void f4add(float4& a, const float4 b) {
    a.x += b.x; a.y += b.y; a.z += b.z; a.w += b.w;
}

__global__ void zero_f_kernel(float* p, int n) {
    int i = blockIdx.x * blockDim.x + threadIdx.x;
    if (i < n) p[i] = 0.f;
}
__global__ void zero_i_kernel(int* p, int n) {
    int i = blockIdx.x * blockDim.x + threadIdx.x;
    if (i < n) p[i] = 0;
}

// ---------------- CSR build ----------------
__global__ void hist_kernel(const int* __restrict__ dst, int* __restrict__ cnt, int e) {
    int i = blockIdx.x * blockDim.x + threadIdx.x;
    if (i < e) atomicAdd(&cnt[dst[i]], 1);
}

__global__ void scan_kernel(const int* __restrict__ cnt, int* __restrict__ rowptr,
                            int* __restrict__ cursor, int n) {
    __shared__ int part[1024];
    int tid = threadIdx.x;
    int chunk = (n + 1023) / 1024;
    int begin = tid * chunk;
    int end = begin + chunk; if (end > n) end = n;
    int s = 0;
    for (int i = begin; i < end && i < n; i++) s += cnt[i];
    part[tid] = s;
    __syncthreads();
    // Hillis-Steele inclusive scan
    for (int off = 1; off < 1024; off <<= 1) {
        int v = 0;
        if (tid >= off) v = part[tid - off];
        __syncthreads();
        part[tid] += v;
        __syncthreads();
    }
    int base = (tid == 0) ? 0 : part[tid - 1];
    for (int i = begin; i < end && i < n; i++) {
        rowptr[i] = base;
        cursor[i] = base;
        base += cnt[i];
    }
    if (tid == 1023) rowptr[n] = part[1023];
}

__global__ void scatter_kernel(const int* __restrict__ src, const int* __restrict__ dst,
                               int* __restrict__ cursor, int* __restrict__ csrsrc, int e) {
    int i = blockIdx.x * blockDim.x + threadIdx.x;
    if (i < e) {
        int p = atomicAdd(&cursor[dst[i]], 1);
        csrsrc[p] = src[i];
    }
}

// d[r] = sum over edges into r of indeg(src) = (A^2 * 1)[r]
__global__ void degsum_kernel(const int* __restrict__ rowptr, const int* __restrict__ srcs,
                              const int* __restrict__ cnt, float* __restrict__ d, int n) {
    int r = blockIdx.x * blockDim.x + threadIdx.x;
    if (r >= n) return;
    int b = rowptr[r], e = rowptr[r + 1];
    float s = 0.f;
    for (int i = b; i < e; i++) s += (float)cnt[srcs[i]];
    d[r] = s;
}

// ---------------- aggregation: out[r,:] = sum_{e in row r} in[src[e],:] ----------------
__global__ void agg_kernel(const float4* __restrict__ in, float4* __restrict__ out,
                           const int* __restrict__ rowptr, const int* __restrict__ srcs) {
    int r = blockIdx.x;
    int j = threadIdx.x;  // 0..63 (float4 columns)
    int b = __ldg(&rowptr[r]);
    int e = __ldg(&rowptr[r + 1]);
    float4 a0 = {0, 0, 0, 0}, a1 = {0, 0, 0, 0}, a2 = {0, 0, 0, 0}, a3 = {0, 0, 0, 0};
    int i = b;
    for (; i + 3 < e; i += 4) {
        int s0 = srcs[i], s1 = srcs[i + 1], s2 = srcs[i + 2], s3 = srcs[i + 3];
        float4 v0 = in[s0 * FF4 + j];
        float4 v1 = in[s1 * FF4 + j];
        float4 v2 = in[s2 * FF4 + j];
        float4 v3 = in[s3 * FF4 + j];
        f4add(a0, v0); f4add(a1, v1); f4add(a2, v2); f4add(a3, v3);
    }
    for (; i < e; i++) {
        float4 v = in[srcs[i] * FF4 + j];
        f4add(a0, v);
    }
    float4 o;
    o.x = a0.x + a1.x + a2.x + a3.x;
    o.y = a0.y + a1.y + a2.y + a3.y;
    o.z = a0.z + a1.z + a2.z + a3.z;
    o.w = a0.w + a1.w + a2.w + a3.w;
    out[r * FF4 + j] = o;
}

// ---------------- main SGEMM: C[MxFF] = A[MxFF] * B[FFxFF] + bias ----------------
__global__ __launch_bounds__(256) void sgemm_bias_kernel(
    const float* __restrict__ A, const float* __restrict__ B,
    const float* __restrict__ bias, float* __restrict__ C, int M) {
    __shared__ float As[8][128];
    __shared__ float Bs[8][128];
    int tid = threadIdx.x;
    int bm = blockIdx.x * 128;
    int bn = blockIdx.y * 128;
    int tx = tid & 15, ty = tid >> 4;
    int arow = tid >> 1;
    int akq  = (tid & 1) * 4;
    int brow = tid >> 5;
    int bcol = (tid & 31) * 4;
    float acc[8][8] = {};
    for (int k0 = 0; k0 < FF; k0 += 8) {
        float4 av = {0, 0, 0, 0};
        if (bm + arow < M)
            av = *(const float4*)&A[(bm + arow) * FF + k0 + akq];
        As[akq + 0][arow] = av.x;
        As[akq + 1][arow] = av.y;
        As[akq + 2][arow] = av.z;
        As[akq + 3][arow] = av.w;
        float4 bv = *(const float4*)&B[(k0 + brow) * FF + bn + bcol];
        *(float4*)&Bs[brow][bcol] = bv;
        __syncthreads();
#pragma unroll
        for (int kk = 0; kk < 8; kk++) {
            float a[8], b[8];
#pragma unroll
            for (int i = 0; i < 8; i++) a[i] = As[kk][ty * 8 + i];
#pragma unroll
            for (int i = 0; i < 8; i++) b[i] = Bs[kk][tx * 8 + i];
#pragma unroll
            for (int r = 0; r < 8; r++)
#pragma unroll
                for (int c = 0; c < 8; c++) acc[r][c] += a[r] * b[c];
        }
        __syncthreads();
    }
#pragma unroll
    for (int r = 0; r < 8; r++) {
        int m = bm + ty * 8 + r;
        if (m < M) {
#pragma unroll
            for (int c = 0; c < 8; c += 4) {
                int n = bn + tx * 8 + c;
                float4 o;
                o.x = acc[r][c + 0] + bias[n + 0];
                o.y = acc[r][c + 1] + bias[n + 1];
                o.z = acc[r][c + 2] + bias[n + 2];
                o.w = acc[r][c + 3] + bias[n + 3];
                *(float4*)&C[m * FF + n] = o;
            }
        }
    }
}

// ---------------- reduction GEMM: C[FFxFF] += A^T * B over K rows (split-K) ----------------
__global__ __launch_bounds__(256) void atgemm_kernel(
    const float* __restrict__ A, const float* __restrict__ B,
    float* __restrict__ C, int Ktot, int KC) {
    __shared__ float As[8][128];
    __shared__ float Bs[8][128];
    int tid = threadIdx.x;
    int bm = blockIdx.x * 128;
    int bn = blockIdx.y * 128;
    int k0 = blockIdx.z * KC;
    int kend = k0 + KC; if (kend > Ktot) kend = Ktot;
    int tx = tid & 15, ty = tid >> 4;
    int lrow = tid >> 5;
    int lcol = (tid & 31) * 4;
    float acc[8][8] = {};
    for (int kb = k0; kb < kend; kb += 8) {
        float4 av = {0, 0, 0, 0}, bv = {0, 0, 0, 0};
        int kr = kb + lrow;
        if (kr < kend) {
            av = *(const float4*)&A[kr * FF + bm + lcol];
            bv = *(const float4*)&B[kr * FF + bn + lcol];
        }
        *(float4*)&As[lrow][lcol] = av;
        *(float4*)&Bs[lrow][lcol] = bv;
        __syncthreads();
#pragma unroll
        for (int kk = 0; kk < 8; kk++) {
            float a[8], b[8];
#pragma unroll
            for (int i = 0; i < 8; i++) a[i] = As[kk][ty * 8 + i];
#pragma unroll
            for (int i = 0; i < 8; i++) b[i] = Bs[kk][tx * 8 + i];
#pragma unroll
            for (int r = 0; r < 8; r++)
#pragma unroll
                for (int c = 0; c < 8; c++) acc[r][c] += a[r] * b[c];
        }
        __syncthreads();
    }
#pragma unroll
    for (int r = 0; r < 8; r++)
#pragma unroll
        for (int c = 0; c < 8; c++)
            atomicAdd(&C[(bm + ty * 8 + r) * FF + bn + tx * 8 + c], acc[r][c]);
}

// ---------------- BN ----------------
__global__ void colstats_kernel(const float* __restrict__ X, float* __restrict__ sum,
                                float* __restrict__ sumsq, int M) {
    int j = threadIdx.x;
    int r0 = blockIdx.x * 256;
    int r1 = r0 + 256; if (r1 > M) r1 = M;
    float s = 0.f, s2 = 0.f;
    for (int r = r0; r < r1; r++) {
        float v = X[r * FF + j];
        s += v; s2 += v * v;
    }
    atomicAdd(&sum[j], s);
    atomicAdd(&sumsq[j], s2);
}

__global__ void bnparam_kernel(const float* sum, const float* sumsq, const float* gamma,
                               const float* beta, float* s, float* t, float invN) {
    int j = threadIdx.x;
    float m = sum[j] * invN;
    float v = sumsq[j] * invN - m * m;
    float sc = gamma[j] * rsqrtf(v + 1e-5f);
    s[j] = sc;
    t[j] = beta[j] - m * sc;
}

__global__ void bnapply_kernel(float* __restrict__ X, const float* __restrict__ s,
                               const float* __restrict__ t) {
    int j = threadIdx.x;
    int r = blockIdx.x;
    float v = X[r * FF + j];
    X[r * FF + j] = v * s[j] + t[j];
}

// ---------------- column reductions for rank-1 terms ----------------
// a[j] += sum_r Q[r,j]*w[r];  c[j] += sum_r Q[r,j]
__global__ void colw_kernel(const float* __restrict__ Q, const float* __restrict__ w,
                            float* __restrict__ a, float* __restrict__ c, int M) {
    int j = threadIdx.x;
    int r0 = blockIdx.x * 256;
    int r1 = r0 + 256; if (r1 > M) r1 = M;
    float sa = 0.f, sc = 0.f;
    for (int r = r0; r < r1; r++) {
        float v = Q[r * FF + j];
        sa += v * w[r];
        sc += v;
    }
    atomicAdd(&a[j], sa);
    atomicAdd(&c[j], sc);
}

// scal[0] += d1.d2, scal[1] += sum d1, scal[2] += sum d2
__global__ void dots_kernel(const float* __restrict__ d1, const float* __restrict__ d2,
                            float* __restrict__ scal, int n) {
    int gid = blockIdx.x * blockDim.x + threadIdx.x;
    int stride = gridDim.x * blockDim.x;
    float a = 0.f, s1 = 0.f, s2 = 0.f;
    for (int i = gid; i < n; i += stride) {
        float x = d1[i], y = d2[i];
        a += x * y; s1 += x; s2 += y;
    }
    for (int o = 16; o; o >>= 1) {
        a  += __shfl_xor_sync(0xffffffffu, a, o);
        s1 += __shfl_xor_sync(0xffffffffu, s1, o);
        s2 += __shfl_xor_sync(0xffffffffu, s2, o);
    }
    if ((threadIdx.x & 31) == 0) {
        atomicAdd(&scal[0], a);
        atomicAdd(&scal[1], s1);
        atomicAdd(&scal[2], s2);
    }
}

// ---------------- small 256x256x256 GEMMs ----------------
__global__ void mm256_nn_kernel(const float* __restrict__ A, const float* __restrict__ B,
                                float* __restrict__ C) {
    __shared__ float As[16][16];
    __shared__ float Bs[16][17];
    int tx = threadIdx.x, ty = threadIdx.y;
    int row = blockIdx.y * 16 + ty;
    int col = blockIdx.x * 16 + tx;
    float acc = 0.f;
    for (int k0 = 0; k0 < FF; k0 += 16) {
        As[ty][tx] = A[row * FF + k0 + tx];
        Bs[ty][tx] = B[(k0 + ty) * FF + col];
        __syncthreads();
#pragma unroll
        for (int kk = 0; kk < 16; kk++) acc += As[ty][kk] * Bs[kk][tx];
        __syncthreads();
    }
    C[row * FF + col] = acc;
}

__global__ void mm256_nt_kernel(const float* __restrict__ A, const float* __restrict__ B,
                                float* __restrict__ C) {
    __shared__ float As[16][16];
    __shared__ float Bs[16][17];
    int tx = threadIdx.x, ty = threadIdx.y;
    int row = blockIdx.y * 16 + ty;
    int col = blockIdx.x * 16 + tx;
    float acc = 0.f;
    for (int k0 = 0; k0 < FF; k0 += 16) {
        As[ty][tx] = A[row * FF + k0 + tx];
        Bs[ty][tx] = B[(blockIdx.x * 16 + tx) * FF + k0 + ty];  // B[col][k]
        __syncthreads();
#pragma unroll
        for (int kk = 0; kk < 16; kk++) acc += As[ty][kk] * Bs[kk][tx];
        __syncthreads();
    }
    C[row * FF + col] = acc;
}

// y = M x  (256x256)
__global__ void matvec256_kernel(const float* __restrict__ Mm, const float* __restrict__ x,
                                 float* __restrict__ y) {
    int r = blockIdx.x;
    int lane = threadIdx.x;
    float a = 0.f;
    for (int k = lane; k < FF; k += 32) a += Mm[r * FF + k] * x[k];
    for (int o = 16; o; o >>= 1) a += __shfl_xor_sync(0xffffffffu, a, o);
    if (lane == 0) y[r] = a;
}

// Wt[k][n] = W[n][k]
__global__ void transpose256_kernel(const float* __restrict__ W, float* __restrict__ Wt) {
    int j = threadIdx.x;  // n
    int i = blockIdx.x;   // k
    Wt[i * FF + j] = W[j * FF + i];
}

// ---------------- final assembly ----------------
__global__ void assemble_kernel(const float* __restrict__ R, const float* __restrict__ u,
                                const float* __restrict__ b3, const float* __restrict__ v1,
                                const float* __restrict__ w1, const float* __restrict__ v2,
                                const float* __restrict__ w2, const float* __restrict__ scal,
                                float* __restrict__ out) {
    int i = blockIdx.x, j = threadIdx.x;
    float alpha = scal[0], sig1 = scal[1], sig2 = scal[2];
    float ui = u[i], uj = u[j], bi = b3[i], bj = b3[j];
    out[i * FF + j] = R[i * FF + j]
                    + v1[i] * uj + w1[i] * bj
                    + ui * v2[j] + alpha * ui * uj + sig1 * ui * bj
                    + bi * w2[j] + sig2 * bi * uj
                    + (float)NN * bi * bj;
}

// ---------------- host ----------------
extern "C" void kernel_launch(void* const* d_in, const int* in_sizes, int n_in,
                              void* d_out, int out_size) {
    (void)in_sizes; (void)n_in; (void)out_size;
    const float* feature = (const float*)d_in[0];
    const int* src1 = (const int*)d_in[1];
    const int* dst1 = (const int*)d_in[2];
    const int* src2 = (const int*)d_in[3];
    const int* dst2 = (const int*)d_in[4];
    const float* W1 = (const float*)d_in[5];
    const float* b1 = (const float*)d_in[6];
    const float* W2 = (const float*)d_in[7];
    const float* b2 = (const float*)d_in[8];
    const float* W3 = (const float*)d_in[9];
    const float* b3 = (const float*)d_in[10];
    const float* gamma = (const float*)d_in[11];
    const float* beta = (const float*)d_in[12];
    float* out = (float*)d_out;

    float *T0, *T1, *Q1, *d1, *d2, *S, *W23, *Wt, *Tm, *R;
    float *sum, *sumsq, *bns, *bnt, *a1, *c1, *a2, *c2, *u, *v1, *w1, *v2, *w2, *scal;
    int *cnt, *rowptr, *cursor, *csrsrc;
    cudaGetSymbolAddress((void**)&T0, g_T0);
    cudaGetSymbolAddress((void**)&T1, g_T1);
    cudaGetSymbolAddress((void**)&Q1, g_Q1buf);
    cudaGetSymbolAddress((void**)&cnt, g_cnt);
    cudaGetSymbolAddress((void**)&rowptr, g_rowptr);
    cudaGetSymbolAddress((void**)&cursor, g_cursor);
    cudaGetSymbolAddress((void**)&csrsrc, g_csrsrc);
    cudaGetSymbolAddress((void**)&d1, g_d1);
    cudaGetSymbolAddress((void**)&d2, g_d2);
    cudaGetSymbolAddress((void**)&S, g_S);
    cudaGetSymbolAddress((void**)&W23, g_W23);
    cudaGetSymbolAddress((void**)&Wt, g_Wt);
    cudaGetSymbolAddress((void**)&Tm, g_Tm);
    cudaGetSymbolAddress((void**)&R, g_R);
    cudaGetSymbolAddress((void**)&sum, g_sum);
    cudaGetSymbolAddress((void**)&sumsq, g_sumsq);
    cudaGetSymbolAddress((void**)&bns, g_bns);
    cudaGetSymbolAddress((void**)&bnt, g_bnt);
    cudaGetSymbolAddress((void**)&a1, g_a1);
    cudaGetSymbolAddress((void**)&c1, g_c1);
    cudaGetSymbolAddress((void**)&a2, g_a2);
    cudaGetSymbolAddress((void**)&c2, g_c2);
    cudaGetSymbolAddress((void**)&u, g_u);
    cudaGetSymbolAddress((void**)&v1, g_v1);
    cudaGetSymbolAddress((void**)&w1, g_w1);
    cudaGetSymbolAddress((void**)&v2, g_v2);
    cudaGetSymbolAddress((void**)&w2, g_w2);
    cudaGetSymbolAddress((void**)&scal, g_scal);

    const int EG = (EE + 255) / 256;   // 3125
    const int NG = (NN + 255) / 256;   // 196
    dim3 mmGrid(16, 16), mmBlk(16, 16);

    // graph-independent precompute
    transpose256_kernel<<<FF, FF>>>(W1, Wt);            // Wt = W1^T
    mm256_nn_kernel<<<mmGrid, mmBlk>>>(W3, W2, W23);    // W23 = W3*W2
    matvec256_kernel<<<FF, 32>>>(W3, b2, u);            // u = W3*b2

    for (int br = 0; br < 2; br++) {
        const int* src = br ? src2 : src1;
        const int* dst = br ? dst2 : dst1;
        float* dvec = br ? d2 : d1;

        // CSR build (per call: deterministic work)
        zero_i_kernel<<<NG, 256>>>(cnt, NN);
        hist_kernel<<<EG, 256>>>(dst, cnt, EE);
        scan_kernel<<<1, 1024>>>(cnt, rowptr, cursor, NN);
        scatter_kernel<<<EG, 256>>>(src, dst, cursor, csrsrc, EE);
        degsum_kernel<<<NG, 256>>>(rowptr, csrsrc, cnt, dvec, NN);  // d = A^2 * 1

        // P = A^2 f
        agg_kernel<<<NN, 64>>>((const float4*)feature, (float4*)T0, rowptr, csrsrc);
        agg_kernel<<<NN, 64>>>((const float4*)T0, (float4*)T1, rowptr, csrsrc);

        // X1 = P*W1^T + b1
        sgemm_bias_kernel<<<dim3((NN + 127) / 128, 2), 256>>>(T1, Wt, b1, T0, NN);

        // BN
        zero_f_kernel<<<1, 256>>>(sum, FF);
        zero_f_kernel<<<1, 256>>>(sumsq, FF);
        colstats_kernel<<<NG, 256>>>(T0, sum, sumsq, NN);
        bnparam_kernel<<<1, 256>>>(sum, sumsq, gamma, beta, bns, bnt, 1.0f / (float)NN);
        bnapply_kernel<<<NN, 256>>>(T0, bns, bnt);      // Y in T0

        // Q = A^4 Y
        agg_kernel<<<NN, 64>>>((const float4*)T0, (float4*)T1, rowptr, csrsrc);
        agg_kernel<<<NN, 64>>>((const float4*)T1, (float4*)T0, rowptr, csrsrc);
        agg_kernel<<<NN, 64>>>((const float4*)T0, (float4*)T1, rowptr, csrsrc);
        agg_kernel<<<NN, 64>>>((const float4*)T1, (float4*)(br ? T0 : Q1), rowptr, csrsrc);
        // branch 0: Q1 in g_Q1buf;  branch 1: Q2 in T0
    }

    // S = Q1^T Q2 (split-K with atomics)
    zero_f_kernel<<<FF, 256>>>(S, FF * FF);
    atgemm_kernel<<<dim3(2, 2, (NN + 511) / 512), 256>>>(Q1, T0, S, NN, 512);

    // rank-1 pieces
    zero_f_kernel<<<1, 256>>>(a1, FF);
    zero_f_kernel<<<1, 256>>>(c1, FF);
    zero_f_kernel<<<1, 256>>>(a2, FF);
    zero_f_kernel<<<1, 256>>>(c2, FF);
    zero_f_kernel<<<1, 256>>>(scal, 4);
    colw_kernel<<<NG, 256>>>(Q1, d2, a1, c1, NN);   // a1=Q1^T d2, c1=Q1^T 1
    colw_kernel<<<NG, 256>>>(T0, d1, a2, c2, NN);   // a2=Q2^T d1, c2=Q2^T 1
    dots_kernel<<<98, 256>>>(d1, d2, scal, NN);     // alpha, sum d1, sum d2

    // R = W23 * S * W23^T
    mm256_nn_kernel<<<mmGrid, mmBlk>>>(W23, S, Tm);
    mm256_nt_kernel<<<mmGrid, mmBlk>>>(Tm, W23, R);

    matvec256_kernel<<<FF, 32>>>(W23, a1, v1);
    matvec256_kernel<<<FF, 32>>>(W23, c1, w1);
    matvec256_kernel<<<FF, 32>>>(W23, a2, v2);
    matvec256_kernel<<<FF, 32>>>(W23, c2, w2);

    assemble_kernel<<<FF, FF>>>(R, u, b3, v1, w1, v2, w2, scal, out);
}

// round 11
// speedup vs baseline: 1.2577x; 1.2577x over previous
#include <cuda_runtime.h>
#include <cuda_bf16.h>

#define NN 50000
#define EE 800000
#define FF 256
#define FF4 64

// ---------------- device scratch (static: no cudaMalloc allowed) ----------------
__device__ float g_T0[NN * FF];
__device__ float g_T1[NN * FF];
__device__ float g_Q1buf[NN * FF];
__device__ int   g_cnt[NN];
__device__ int   g_rowptr[NN + 1];
__device__ int   g_cursor[NN];
__device__ int   g_csrsrc[EE];
__device__ float g_d1[NN];
__device__ float g_d2[NN];
__device__ float g_S[FF * FF];
__device__ float g_W23[FF * FF];
__device__ float g_Tm[FF * FF];
__device__ float g_R[FF * FF];
__device__ float g_sum[FF], g_sumsq[FF], g_bns[FF], g_bnt[FF];
__device__ float g_a1[FF], g_c1[FF], g_a2[FF], g_c2[FF];
__device__ float g_u[FF], g_v1[FF], g_w1[FF], g_v2[FF], g_w2[FF];
__device__ float g_scal[4];

// ---------------- helpers ----------------
__device__ __forceinline__ void f4add(float4& a, const float4 b) {
    a.x += b.x; a.y += b.y; a.z += b.z; a.w += b.w;
}

__global__ void zero_f_kernel(float* p, int n) {
    int i = blockIdx.x * blockDim.x + threadIdx.x;
    if (i < n) p[i] = 0.f;
}
__global__ void zero_i_kernel(int* p, int n) {
    int i = blockIdx.x * blockDim.x + threadIdx.x;
    if (i < n) p[i] = 0;
}

// ---------------- CSR build ----------------
__global__ void hist_kernel(const int* __restrict__ dst, int* __restrict__ cnt, int e) {
    int i = blockIdx.x * blockDim.x + threadIdx.x;
    if (i < e) atomicAdd(&cnt[dst[i]], 1);
}

__global__ void scan_kernel(const int* __restrict__ cnt, int* __restrict__ rowptr,
                            int* __restrict__ cursor, int n) {
    __shared__ int part[1024];
    int tid = threadIdx.x;
    int chunk = (n + 1023) / 1024;
    int begin = tid * chunk;
    int end = begin + chunk; if (end > n) end = n;
    int s = 0;
    for (int i = begin; i < end && i < n; i++) s += cnt[i];
    part[tid] = s;
    __syncthreads();
    for (int off = 1; off < 1024; off <<= 1) {
        int v = 0;
        if (tid >= off) v = part[tid - off];
        __syncthreads();
        part[tid] += v;
        __syncthreads();
    }
    int base = (tid == 0) ? 0 : part[tid - 1];
    for (int i = begin; i < end && i < n; i++) {
        rowptr[i] = base;
        cursor[i] = base;
        base += cnt[i];
    }
    if (tid == 1023) rowptr[n] = part[1023];
}

__global__ void scatter_kernel(const int* __restrict__ src, const int* __restrict__ dst,
                               int* __restrict__ cursor, int* __restrict__ csrsrc, int e) {
    int i = blockIdx.x * blockDim.x + threadIdx.x;
    if (i < e) {
        int p = atomicAdd(&cursor[dst[i]], 1);
        csrsrc[p] = src[i];
    }
}

__global__ void degsum_kernel(const int* __restrict__ rowptr, const int* __restrict__ srcs,
                              const int* __restrict__ cnt, float* __restrict__ d, int n) {
    int r = blockIdx.x * blockDim.x + threadIdx.x;
    if (r >= n) return;
    int b = rowptr[r], e = rowptr[r + 1];
    float s = 0.f;
    for (int i = b; i < e; i++) s += (float)cnt[srcs[i]];
    d[r] = s;
}

// ---------------- aggregation: out[r,:] = sum_{e in row r} in[src[e],:] ----------------
__global__ void agg_kernel(const float4* __restrict__ in, float4* __restrict__ out,
                           const int* __restrict__ rowptr, const int* __restrict__ srcs) {
    int r = blockIdx.x;
    int j = threadIdx.x;  // 0..63 (float4 columns)
    int b = __ldg(&rowptr[r]);
    int e = __ldg(&rowptr[r + 1]);
    float4 a0 = {0, 0, 0, 0}, a1 = {0, 0, 0, 0}, a2 = {0, 0, 0, 0}, a3 = {0, 0, 0, 0};
    int i = b;
    for (; i + 3 < e; i += 4) {
        int s0 = srcs[i], s1 = srcs[i + 1], s2 = srcs[i + 2], s3 = srcs[i + 3];
        float4 v0 = in[s0 * FF4 + j];
        float4 v1 = in[s1 * FF4 + j];
        float4 v2 = in[s2 * FF4 + j];
        float4 v3 = in[s3 * FF4 + j];
        f4add(a0, v0); f4add(a1, v1); f4add(a2, v2); f4add(a3, v3);
    }
    for (; i < e; i++) {
        float4 v = in[srcs[i] * FF4 + j];
        f4add(a0, v);
    }
    float4 o;
    o.x = a0.x + a1.x + a2.x + a3.x;
    o.y = a0.y + a1.y + a2.y + a3.y;
    o.z = a0.z + a1.z + a2.z + a3.z;
    o.w = a0.w + a1.w + a2.w + a3.w;
    out[r * FF4 + j] = o;
}

// ================= tensor-core split-bf16 GEMM machinery =================
// SMEM tiles: 128 rows x 16 k-values, stored as 12 b32 words/row (8 data + 4 pad)
// word w of row r holds bf16 pair (k=2w low half, k=2w+1 high half).
// 12-word (48B) row pitch makes all fragment loads bank-conflict-free.

#define TPITCH 12

__device__ __forceinline__ void split2(float x0, float x1, unsigned& hi, unsigned& lo) {
    __nv_bfloat16 h0 = __float2bfloat16(x0);
    __nv_bfloat16 h1 = __float2bfloat16(x1);
    __nv_bfloat16 l0 = __float2bfloat16(x0 - __bfloat162float(h0));
    __nv_bfloat16 l1 = __float2bfloat16(x1 - __bfloat162float(h1));
    hi = ((unsigned)__bfloat16_as_ushort(h1) << 16) | (unsigned)__bfloat16_as_ushort(h0);
    lo = ((unsigned)__bfloat16_as_ushort(l1) << 16) | (unsigned)__bfloat16_as_ushort(l0);
}

__device__ __forceinline__ void mma16816(float* c, const unsigned* a, const unsigned* b) {
    asm volatile(
        "mma.sync.aligned.m16n8k16.row.col.f32.bf16.bf16.f32 "
        "{%0,%1,%2,%3}, {%4,%5,%6,%7}, {%8,%9}, {%0,%1,%2,%3};\n"
        : "+f"(c[0]), "+f"(c[1]), "+f"(c[2]), "+f"(c[3])
        : "r"(a[0]), "r"(a[1]), "r"(a[2]), "r"(a[3]), "r"(b[0]), "r"(b[1]));
}

// 8 warps: 2 (m) x 4 (n); warp tile 64x32; per warp 4x4 m16n8 tiles.
__device__ __forceinline__ void mma_compute(
    const unsigned* __restrict__ AsHi, const unsigned* __restrict__ AsLo,
    const unsigned* __restrict__ BsHi, const unsigned* __restrict__ BsLo,
    float c[4][4][4], int wid, int lane) {
    int wm = (wid >> 2) * 64;
    int wn = (wid & 3) * 32;
    int g = lane >> 2, q = lane & 3;
    unsigned ahi[4][4], alo[4][4];
#pragma unroll
    for (int i = 0; i < 4; i++) {
        int r0 = (wm + i * 16 + g) * TPITCH;
        int r1 = r0 + 8 * TPITCH;
        ahi[i][0] = AsHi[r0 + q];     ahi[i][1] = AsHi[r1 + q];
        ahi[i][2] = AsHi[r0 + 4 + q]; ahi[i][3] = AsHi[r1 + 4 + q];
        alo[i][0] = AsLo[r0 + q];     alo[i][1] = AsLo[r1 + q];
        alo[i][2] = AsLo[r0 + 4 + q]; alo[i][3] = AsLo[r1 + 4 + q];
    }
#pragma unroll
    for (int j = 0; j < 4; j++) {
        int nb = (wn + j * 8 + g) * TPITCH;
        unsigned bh[2], bl[2];
        bh[0] = BsHi[nb + q]; bh[1] = BsHi[nb + 4 + q];
        bl[0] = BsLo[nb + q]; bl[1] = BsLo[nb + 4 + q];
#pragma unroll
        for (int i = 0; i < 4; i++) {
            mma16816(c[i][j], ahi[i], bh);
            mma16816(c[i][j], ahi[i], bl);
            mma16816(c[i][j], alo[i], bh);
        }
    }
}

// ---------------- C[MxFF] = A[MxFF] * W^T + bias (tensor core) ----------------
// A row-major [M][256]; W row-major [256][256]; B-operand(k,n) = W[n][k].
__global__ __launch_bounds__(256) void sgemm_tc_kernel(
    const float* __restrict__ A, const float* __restrict__ W,
    const float* __restrict__ bias, float* __restrict__ C, int M) {
    __shared__ unsigned AsHi[128 * TPITCH], AsLo[128 * TPITCH];
    __shared__ unsigned BsHi[128 * TPITCH], BsLo[128 * TPITCH];
    int t = threadIdx.x;
    int bm = blockIdx.x * 128, bn = blockIdx.y * 128;
    int wid = t >> 5, lane = t & 31;
    float c[4][4][4];
#pragma unroll
    for (int i = 0; i < 4; i++)
#pragma unroll
        for (int j = 0; j < 4; j++)
#pragma unroll
            for (int v = 0; v < 4; v++) c[i][j][v] = 0.f;

    int r = t >> 1;              // 0..127
    int kk0 = (t & 1) * 8;       // 0 or 8
    bool aok = (bm + r) < M;
    const float* ap = A + (long)(bm + r) * FF + kk0;
    const float* wp = W + (long)(bn + r) * FF + kk0;

    for (int k0 = 0; k0 < FF; k0 += 16) {
        float xa[8] = {0, 0, 0, 0, 0, 0, 0, 0}, xb[8];
        if (aok) {
            float4 v0 = *(const float4*)(ap + k0);
            float4 v1 = *(const float4*)(ap + k0 + 4);
            xa[0] = v0.x; xa[1] = v0.y; xa[2] = v0.z; xa[3] = v0.w;
            xa[4] = v1.x; xa[5] = v1.y; xa[6] = v1.z; xa[7] = v1.w;
        }
        {
            float4 v0 = *(const float4*)(wp + k0);
            float4 v1 = *(const float4*)(wp + k0 + 4);
            xb[0] = v0.x; xb[1] = v0.y; xb[2] = v0.z; xb[3] = v0.w;
            xb[4] = v1.x; xb[5] = v1.y; xb[6] = v1.z; xb[7] = v1.w;
        }
        __syncthreads();   // previous iter's fragment reads done
#pragma unroll
        for (int s = 0; s < 8; s += 2) {
            unsigned hi, lo;
            int w = r * TPITCH + (kk0 + s) / 2;
            split2(xa[s], xa[s + 1], hi, lo);
            AsHi[w] = hi; AsLo[w] = lo;
            split2(xb[s], xb[s + 1], hi, lo);
            BsHi[w] = hi; BsLo[w] = lo;
        }
        __syncthreads();
        mma_compute(AsHi, AsLo, BsHi, BsLo, c, wid, lane);
    }

    // epilogue: add bias, direct store
    int g = lane >> 2, q = lane & 3;
    int wm = bm + (wid >> 2) * 64;
    int wn = bn + (wid & 3) * 32;
#pragma unroll
    for (int i = 0; i < 4; i++) {
#pragma unroll
        for (int j = 0; j < 4; j++) {
            int col = wn + j * 8 + q * 2;
            float b0 = bias[col], b1 = bias[col + 1];
            int row0 = wm + i * 16 + g;
            if (row0 < M)
                *(float2*)&C[(long)row0 * FF + col] =
                    make_float2(c[i][j][0] + b0, c[i][j][1] + b1);
            int row1 = row0 + 8;
            if (row1 < M)
                *(float2*)&C[(long)row1 * FF + col] =
                    make_float2(c[i][j][2] + b0, c[i][j][3] + b1);
        }
    }
}

// ---------------- C[FFxFF] += A^T * B over K rows (tensor core, split-K) ----------------
__global__ __launch_bounds__(256) void atgemm_tc_kernel(
    const float* __restrict__ A, const float* __restrict__ B,
    float* __restrict__ C, int Ktot, int KC) {
    __shared__ unsigned AsHi[128 * TPITCH], AsLo[128 * TPITCH];
    __shared__ unsigned BsHi[128 * TPITCH], BsLo[128 * TPITCH];
    int t = threadIdx.x;
    int bm = blockIdx.x * 128, bn = blockIdx.y * 128;
    int k0base = blockIdx.z * KC;
    int kend = k0base + KC; if (kend > Ktot) kend = Ktot;
    int wid = t >> 5, lane = t & 31;
    float c[4][4][4];
#pragma unroll
    for (int i = 0; i < 4; i++)
#pragma unroll
        for (int j = 0; j < 4; j++)
#pragma unroll
            for (int v = 0; v < 4; v++) c[i][j][v] = 0.f;

    int m = t & 127;            // row within tile (plays m for A, n for B)
    int khalf = t >> 7;         // 0/1 -> k offset 0 or 8

    for (int k0 = k0base; k0 < k0base + KC; k0 += 16) {
        float xa[8], xb[8];
#pragma unroll
        for (int s = 0; s < 8; s++) {
            int kr = k0 + khalf * 8 + s;
            bool ok = kr < kend;
            xa[s] = ok ? A[(long)kr * FF + bm + m] : 0.f;
            xb[s] = ok ? B[(long)kr * FF + bn + m] : 0.f;
        }
        __syncthreads();
#pragma unroll
        for (int s = 0; s < 8; s += 2) {
            unsigned hi, lo;
            int w = m * TPITCH + khalf * 4 + s / 2;
            split2(xa[s], xa[s + 1], hi, lo);
            AsHi[w] = hi; AsLo[w] = lo;
            split2(xb[s], xb[s + 1], hi, lo);
            BsHi[w] = hi; BsLo[w] = lo;
        }
        __syncthreads();
        mma_compute(AsHi, AsLo, BsHi, BsLo, c, wid, lane);
    }

    // epilogue: atomic accumulate into C
    int g = lane >> 2, q = lane & 3;
    int wm = bm + (wid >> 2) * 64;
    int wn = bn + (wid & 3) * 32;
#pragma unroll
    for (int i = 0; i < 4; i++) {
#pragma unroll
        for (int j = 0; j < 4; j++) {
            int col = wn + j * 8 + q * 2;
            int row0 = wm + i * 16 + g;
            int row1 = row0 + 8;
            atomicAdd(&C[(long)row0 * FF + col], c[i][j][0]);
            atomicAdd(&C[(long)row0 * FF + col + 1], c[i][j][1]);
            atomicAdd(&C[(long)row1 * FF + col], c[i][j][2]);
            atomicAdd(&C[(long)row1 * FF + col + 1], c[i][j][3]);
        }
    }
}

// ---------------- BN ----------------
__global__ void colstats_kernel(const float* __restrict__ X, float* __restrict__ sum,
                                float* __restrict__ sumsq, int M) {
    int j = threadIdx.x;
    int r0 = blockIdx.x * 256;
    int r1 = r0 + 256; if (r1 > M) r1 = M;
    float s = 0.f, s2 = 0.f;
    for (int r = r0; r < r1; r++) {
        float v = X[r * FF + j];
        s += v; s2 += v * v;
    }
    atomicAdd(&sum[j], s);
    atomicAdd(&sumsq[j], s2);
}

__global__ void bnparam_kernel(const float* sum, const float* sumsq, const float* gamma,
                               const float* beta, float* s, float* t, float invN) {
    int j = threadIdx.x;
    float m = sum[j] * invN;
    float v = sumsq[j] * invN - m * m;
    float sc = gamma[j] * rsqrtf(v + 1e-5f);
    s[j] = sc;
    t[j] = beta[j] - m * sc;
}

__global__ void bnapply_kernel(float* __restrict__ X, const float* __restrict__ s,
                               const float* __restrict__ t) {
    int j = threadIdx.x;
    int r = blockIdx.x;
    float v = X[r * FF + j];
    X[r * FF + j] = v * s[j] + t[j];
}

// ---------------- column reductions for rank-1 terms ----------------
__global__ void colw_kernel(const float* __restrict__ Q, const float* __restrict__ w,
                            float* __restrict__ a, float* __restrict__ c, int M) {
    int j = threadIdx.x;
    int r0 = blockIdx.x * 256;
    int r1 = r0 + 256; if (r1 > M) r1 = M;
    float sa = 0.f, sc = 0.f;
    for (int r = r0; r < r1; r++) {
        float v = Q[r * FF + j];
        sa += v * w[r];
        sc += v;
    }
    atomicAdd(&a[j], sa);
    atomicAdd(&c[j], sc);
}

__global__ void dots_kernel(const float* __restrict__ d1, const float* __restrict__ d2,
                            float* __restrict__ scal, int n) {
    int gid = blockIdx.x * blockDim.x + threadIdx.x;
    int stride = gridDim.x * blockDim.x;
    float a = 0.f, s1 = 0.f, s2 = 0.f;
    for (int i = gid; i < n; i += stride) {
        float x = d1[i], y = d2[i];
        a += x * y; s1 += x; s2 += y;
    }
    for (int o = 16; o; o >>= 1) {
        a  += __shfl_xor_sync(0xffffffffu, a, o);
        s1 += __shfl_xor_sync(0xffffffffu, s1, o);
        s2 += __shfl_xor_sync(0xffffffffu, s2, o);
    }
    if ((threadIdx.x & 31) == 0) {
        atomicAdd(&scal[0], a);
        atomicAdd(&scal[1], s1);
        atomicAdd(&scal[2], s2);
    }
}

// ---------------- small 256x256x256 GEMMs ----------------
__global__ void mm256_nn_kernel(const float* __restrict__ A, const float* __restrict__ B,
                                float* __restrict__ C) {
    __shared__ float As[16][16];
    __shared__ float Bs[16][17];
    int tx = threadIdx.x, ty = threadIdx.y;
    int row = blockIdx.y * 16 + ty;
    int col = blockIdx.x * 16 + tx;
    float acc = 0.f;
    for (int k0 = 0; k0 < FF; k0 += 16) {
        As[ty][tx] = A[row * FF + k0 + tx];
        Bs[ty][tx] = B[(k0 + ty) * FF + col];
        __syncthreads();
#pragma unroll
        for (int kk = 0; kk < 16; kk++) acc += As[ty][kk] * Bs[kk][tx];
        __syncthreads();
    }
    C[row * FF + col] = acc;
}

__global__ void mm256_nt_kernel(const float* __restrict__ A, const float* __restrict__ B,
                                float* __restrict__ C) {
    __shared__ float As[16][16];
    __shared__ float Bs[16][17];
    int tx = threadIdx.x, ty = threadIdx.y;
    int row = blockIdx.y * 16 + ty;
    int col = blockIdx.x * 16 + tx;
    float acc = 0.f;
    for (int k0 = 0; k0 < FF; k0 += 16) {
        As[ty][tx] = A[row * FF + k0 + tx];
        Bs[ty][tx] = B[(blockIdx.x * 16 + tx) * FF + k0 + ty];  // B[col][k]
        __syncthreads();
#pragma unroll
        for (int kk = 0; kk < 16; kk++) acc += As[ty][kk] * Bs[kk][tx];
        __syncthreads();
    }
    C[row * FF + col] = acc;
}

__global__ void matvec256_kernel(const float* __restrict__ Mm, const float* __restrict__ x,
                                 float* __restrict__ y) {
    int r = blockIdx.x;
    int lane = threadIdx.x;
    float a = 0.f;
    for (int k = lane; k < FF; k += 32) a += Mm[r * FF + k] * x[k];
    for (int o = 16; o; o >>= 1) a += __shfl_xor_sync(0xffffffffu, a, o);
    if (lane == 0) y[r] = a;
}

// ---------------- final assembly ----------------
__global__ void assemble_kernel(const float* __restrict__ R, const float* __restrict__ u,
                                const float* __restrict__ b3, const float* __restrict__ v1,
                                const float* __restrict__ w1, const float* __restrict__ v2,
                                const float* __restrict__ w2, const float* __restrict__ scal,
                                float* __restrict__ out) {
    int i = blockIdx.x, j = threadIdx.x;
    float alpha = scal[0], sig1 = scal[1], sig2 = scal[2];
    float ui = u[i], uj = u[j], bi = b3[i], bj = b3[j];
    out[i * FF + j] = R[i * FF + j]
                    + v1[i] * uj + w1[i] * bj
                    + ui * v2[j] + alpha * ui * uj + sig1 * ui * bj
                    + bi * w2[j] + sig2 * bi * uj
                    + (float)NN * bi * bj;
}

// ---------------- host ----------------
extern "C" void kernel_launch(void* const* d_in, const int* in_sizes, int n_in,
                              void* d_out, int out_size) {
    (void)in_sizes; (void)n_in; (void)out_size;
    const float* feature = (const float*)d_in[0];
    const int* src1 = (const int*)d_in[1];
    const int* dst1 = (const int*)d_in[2];
    const int* src2 = (const int*)d_in[3];
    const int* dst2 = (const int*)d_in[4];
    const float* W1 = (const float*)d_in[5];
    const float* b1 = (const float*)d_in[6];
    const float* W2 = (const float*)d_in[7];
    const float* b2 = (const float*)d_in[8];
    const float* W3 = (const float*)d_in[9];
    const float* b3 = (const float*)d_in[10];
    const float* gamma = (const float*)d_in[11];
    const float* beta = (const float*)d_in[12];
    float* out = (float*)d_out;

    float *T0, *T1, *Q1, *d1, *d2, *S, *W23, *Tm, *R;
    float *sum, *sumsq, *bns, *bnt, *a1, *c1, *a2, *c2, *u, *v1, *w1, *v2, *w2, *scal;
    int *cnt, *rowptr, *cursor, *csrsrc;
    cudaGetSymbolAddress((void**)&T0, g_T0);
    cudaGetSymbolAddress((void**)&T1, g_T1);
    cudaGetSymbolAddress((void**)&Q1, g_Q1buf);
    cudaGetSymbolAddress((void**)&cnt, g_cnt);
    cudaGetSymbolAddress((void**)&rowptr, g_rowptr);
    cudaGetSymbolAddress((void**)&cursor, g_cursor);
    cudaGetSymbolAddress((void**)&csrsrc, g_csrsrc);
    cudaGetSymbolAddress((void**)&d1, g_d1);
    cudaGetSymbolAddress((void**)&d2, g_d2);
    cudaGetSymbolAddress((void**)&S, g_S);
    cudaGetSymbolAddress((void**)&W23, g_W23);
    cudaGetSymbolAddress((void**)&Tm, g_Tm);
    cudaGetSymbolAddress((void**)&R, g_R);
    cudaGetSymbolAddress((void**)&sum, g_sum);
    cudaGetSymbolAddress((void**)&sumsq, g_sumsq);
    cudaGetSymbolAddress((void**)&bns, g_bns);
    cudaGetSymbolAddress((void**)&bnt, g_bnt);
    cudaGetSymbolAddress((void**)&a1, g_a1);
    cudaGetSymbolAddress((void**)&c1, g_c1);
    cudaGetSymbolAddress((void**)&a2, g_a2);
    cudaGetSymbolAddress((void**)&c2, g_c2);
    cudaGetSymbolAddress((void**)&u, g_u);
    cudaGetSymbolAddress((void**)&v1, g_v1);
    cudaGetSymbolAddress((void**)&w1, g_w1);
    cudaGetSymbolAddress((void**)&v2, g_v2);
    cudaGetSymbolAddress((void**)&w2, g_w2);
    cudaGetSymbolAddress((void**)&scal, g_scal);

    const int EG = (EE + 255) / 256;   // 3125
    const int NG = (NN + 255) / 256;   // 196
    dim3 mmGrid(16, 16), mmBlk(16, 16);

    // graph-independent precompute
    mm256_nn_kernel<<<mmGrid, mmBlk>>>(W3, W2, W23);    // W23 = W3*W2
    matvec256_kernel<<<FF, 32>>>(W3, b2, u);            // u = W3*b2

    for (int br = 0; br < 2; br++) {
        const int* src = br ? src2 : src1;
        const int* dst = br ? dst2 : dst1;
        float* dvec = br ? d2 : d1;

        // CSR build
        zero_i_kernel<<<NG, 256>>>(cnt, NN);
        hist_kernel<<<EG, 256>>>(dst, cnt, EE);
        scan_kernel<<<1, 1024>>>(cnt, rowptr, cursor, NN);
        scatter_kernel<<<EG, 256>>>(src, dst, cursor, csrsrc, EE);
        degsum_kernel<<<NG, 256>>>(rowptr, csrsrc, cnt, dvec, NN);  // d = A^2 * 1

        // P = A^2 f
        agg_kernel<<<NN, 64>>>((const float4*)feature, (float4*)T0, rowptr, csrsrc);
        agg_kernel<<<NN, 64>>>((const float4*)T0, (float4*)T1, rowptr, csrsrc);

        // X1 = P*W1^T + b1  (tensor core, split-bf16)
        sgemm_tc_kernel<<<dim3((NN + 127) / 128, 2), 256>>>(T1, W1, b1, T0, NN);

        // BN
        zero_f_kernel<<<1, 256>>>(sum, FF);
        zero_f_kernel<<<1, 256>>>(sumsq, FF);
        colstats_kernel<<<NG, 256>>>(T0, sum, sumsq, NN);
        bnparam_kernel<<<1, 256>>>(sum, sumsq, gamma, beta, bns, bnt, 1.0f / (float)NN);
        bnapply_kernel<<<NN, 256>>>(T0, bns, bnt);      // Y in T0

        // Q = A^4 Y
        agg_kernel<<<NN, 64>>>((const float4*)T0, (float4*)T1, rowptr, csrsrc);
        agg_kernel<<<NN, 64>>>((const float4*)T1, (float4*)T0, rowptr, csrsrc);
        agg_kernel<<<NN, 64>>>((const float4*)T0, (float4*)T1, rowptr, csrsrc);
        agg_kernel<<<NN, 64>>>((const float4*)T1, (float4*)(br ? T0 : Q1), rowptr, csrsrc);
        // branch 0: Q1 in g_Q1buf;  branch 1: Q2 in T0
    }

    // S = Q1^T Q2 (tensor core split-K with atomics)
    zero_f_kernel<<<FF, 256>>>(S, FF * FF);
    atgemm_tc_kernel<<<dim3(2, 2, 64), 256>>>(Q1, T0, S, NN, 784);

    // rank-1 pieces
    zero_f_kernel<<<1, 256>>>(a1, FF);
    zero_f_kernel<<<1, 256>>>(c1, FF);
    zero_f_kernel<<<1, 256>>>(a2, FF);
    zero_f_kernel<<<1, 256>>>(c2, FF);
    zero_f_kernel<<<1, 256>>>(scal, 4);
    colw_kernel<<<NG, 256>>>(Q1, d2, a1, c1, NN);   // a1=Q1^T d2, c1=Q1^T 1
    colw_kernel<<<NG, 256>>>(T0, d1, a2, c2, NN);   // a2=Q2^T d1, c2=Q2^T 1
    dots_kernel<<<98, 256>>>(d1, d2, scal, NN);     // alpha, sum d1, sum d2

    // R = W23 * S * W23^T
    mm256_nn_kernel<<<mmGrid, mmBlk>>>(W23, S, Tm);
    mm256_nt_kernel<<<mmGrid, mmBlk>>>(Tm, W23, R);

    matvec256_kernel<<<FF, 32>>>(W23, a1, v1);
    matvec256_kernel<<<FF, 32>>>(W23, c1, w1);
    matvec256_kernel<<<FF, 32>>>(W23, a2, v2);
    matvec256_kernel<<<FF, 32>>>(W23, c2, w2);

    assemble_kernel<<<FF, FF>>>(R, u, b3, v1, w1, v2, w2, scal, out);
}

// round 14
// speedup vs baseline: 1.3141x; 1.0448x over previous
#include <cuda_runtime.h>
#include <cuda_bf16.h>

#define NN 50000
#define EE 800000
#define FF 256
#define FF4 64

// ---------------- device scratch (static: no cudaMalloc allowed) ----------------
__device__ float g_T0[NN * FF];
__device__ float g_T1[NN * FF];
__device__ float g_Q1buf[NN * FF];
__device__ int   g_cnt[NN];
__device__ int   g_rowptr[NN + 1];
__device__ int   g_cursor[NN];
__device__ int   g_csrsrc[EE];
__device__ int   g_bsum[64];
__device__ int   g_boff[64];
__device__ float g_e2a[NN], g_e2b[NN], g_e4a[NN], g_e4b[NN], g_tmpv[NN];
__device__ float g_G[FF * FF];
__device__ float g_W23[FF * FF];
__device__ float g_Tm[FF * FF];
__device__ float g_R[FF * FF];
__device__ float g_C[FF * FF];
__device__ float g_R1[FF * FF];
__device__ float g_K1[FF * FF];
__device__ float g_K2[FF * FF];
__device__ float g_W1s[FF * FF];
__device__ float g_m2s[FF], g_s[FF], g_cc[FF];
__device__ float g_u[FF], g_v1[FF], g_v2[FF];
__device__ float g_p1a[FF], g_p1b[FF], g_p1c[FF], g_p2a[FF], g_p2b[FF], g_p2c[FF];
__device__ float g_ga1[FF], g_gb1[FF], g_gc1[FF], g_ha2[FF], g_hb2[FF], g_hc2[FF];
__device__ float g_Av[FF], g_Bv[FF], g_Cv[FF];
__device__ float g_scal[8];

// ---------------- helpers ----------------
__device__ __forceinline__ void f4add(float4& a, const float4 b) {
    a.x += b.x; a.y += b.y; a.z += b.z; a.w += b.w;
}

__global__ void zero_f_kernel(float* p, int n) {
    int i = blockIdx.x * blockDim.x + threadIdx.x;
    if (i < n) p[i] = 0.f;
}
__global__ void zero_i_kernel(int* p, int n) {
    int i = blockIdx.x * blockDim.x + threadIdx.x;
    if (i < n) p[i] = 0;
}

// ---------------- CSR build ----------------
__global__ void hist_kernel(const int* __restrict__ dst, int* __restrict__ cnt, int e) {
    int i = blockIdx.x * blockDim.x + threadIdx.x;
    if (i < e) atomicAdd(&cnt[dst[i]], 1);
}

// 3-phase coalesced scan over cnt[0..NN)
__global__ void scan1_kernel(const int* __restrict__ cnt, int* __restrict__ bsum) {
    __shared__ int sh[1024];
    int tid = threadIdx.x;
    int i = blockIdx.x * 1024 + tid;
    sh[tid] = (i < NN) ? cnt[i] : 0;
    __syncthreads();
    for (int o = 512; o; o >>= 1) {
        if (tid < o) sh[tid] += sh[tid + o];
        __syncthreads();
    }
    if (tid == 0) bsum[blockIdx.x] = sh[0];
}

__global__ void scan2_kernel(const int* __restrict__ bsum, int* __restrict__ boff,
                             int* __restrict__ rowptr, int nb) {
    __shared__ int sh[64];
    int t = threadIdx.x;
    sh[t] = (t < nb) ? bsum[t] : 0;
    __syncthreads();
    for (int o = 1; o < 64; o <<= 1) {
        int v = (t >= o) ? sh[t - o] : 0;
        __syncthreads();
        sh[t] += v;
        __syncthreads();
    }
    if (t < nb) boff[t] = (t == 0) ? 0 : sh[t - 1];
    if (t == nb - 1) rowptr[NN] = sh[t];
}

__global__ void scan3_kernel(const int* __restrict__ cnt, const int* __restrict__ boff,
                             int* __restrict__ rowptr, int* __restrict__ cursor) {
    __shared__ int sh[1024];
    int tid = threadIdx.x;
    int i = blockIdx.x * 1024 + tid;
    int v = (i < NN) ? cnt[i] : 0;
    sh[tid] = v;
    __syncthreads();
    for (int o = 1; o < 1024; o <<= 1) {
        int x = (tid >= o) ? sh[tid - o] : 0;
        __syncthreads();
        sh[tid] += x;
        __syncthreads();
    }
    int excl = sh[tid] - v + boff[blockIdx.x];
    if (i < NN) { rowptr[i] = excl; cursor[i] = excl; }
}

__global__ void scatter_kernel(const int* __restrict__ src, const int* __restrict__ dst,
                               int* __restrict__ cursor, int* __restrict__ csrsrc, int e) {
    int i = blockIdx.x * blockDim.x + threadIdx.x;
    if (i < e) {
        int p = atomicAdd(&cursor[dst[i]], 1);
        csrsrc[p] = src[i];
    }
}

// e2[r] = sum over edges into r of indeg(src) = (A^2 * 1)[r]
__global__ void degsum_kernel(const int* __restrict__ rowptr, const int* __restrict__ srcs,
                              const int* __restrict__ cnt, float* __restrict__ d, int n) {
    int r = blockIdx.x * blockDim.x + threadIdx.x;
    if (r >= n) return;
    int b = rowptr[r], e = rowptr[r + 1];
    float s = 0.f;
    for (int i = b; i < e; i++) s += (float)cnt[srcs[i]];
    d[r] = s;
}

// y[r] = sum over edges into r of x[src]  (one A-hop on a vector)
__global__ void vec_agg_kernel(const float* __restrict__ x, float* __restrict__ y,
                               const int* __restrict__ rowptr, const int* __restrict__ srcs,
                               int n) {
    int r = blockIdx.x * blockDim.x + threadIdx.x;
    if (r >= n) return;
    int b = rowptr[r], e = rowptr[r + 1];
    float s = 0.f;
    for (int i = b; i < e; i++) s += __ldg(&x[srcs[i]]);
    y[r] = s;
}

// ---------------- aggregation: out[r,:] = sum_{e in row r} in[src[e],:] ----------------
__global__ void agg_kernel(const float4* __restrict__ in, float4* __restrict__ out,
                           const int* __restrict__ rowptr, const int* __restrict__ srcs) {
    int r = blockIdx.x;
    int j = threadIdx.x;  // 0..63 (float4 columns)
    int b = __ldg(&rowptr[r]);
    int e = __ldg(&rowptr[r + 1]);
    float4 a0 = {0, 0, 0, 0}, a1 = {0, 0, 0, 0}, a2 = {0, 0, 0, 0}, a3 = {0, 0, 0, 0};
    int i = b;
    for (; i + 3 < e; i += 4) {
        int s0 = srcs[i], s1 = srcs[i + 1], s2 = srcs[i + 2], s3 = srcs[i + 3];
        float4 v0 = in[s0 * FF4 + j];
        float4 v1 = in[s1 * FF4 + j];
        float4 v2 = in[s2 * FF4 + j];
        float4 v3 = in[s3 * FF4 + j];
        f4add(a0, v0); f4add(a1, v1); f4add(a2, v2); f4add(a3, v3);
    }
    for (; i < e; i++) {
        float4 v = in[srcs[i] * FF4 + j];
        f4add(a0, v);
    }
    float4 o;
    o.x = a0.x + a1.x + a2.x + a3.x;
    o.y = a0.y + a1.y + a2.y + a3.y;
    o.z = a0.z + a1.z + a2.z + a3.z;
    o.w = a0.w + a1.w + a2.w + a3.w;
    out[r * FF4 + j] = o;
}

// centered aggregation: out[r,:] = sum_{e in row r} (in[src[e],:] - mbar)
//                              = (A in)[r,:] - cnt[r] * (m2s * invN)
__global__ void agg_center_kernel(const float4* __restrict__ in, float4* __restrict__ out,
                                  const int* __restrict__ rowptr, const int* __restrict__ srcs,
                                  const int* __restrict__ cnt, const float4* __restrict__ m2s4,
                                  float invN) {
    int r = blockIdx.x;
    int j = threadIdx.x;
    int b = __ldg(&rowptr[r]);
    int e = __ldg(&rowptr[r + 1]);
    float4 a0 = {0, 0, 0, 0}, a1 = {0, 0, 0, 0}, a2 = {0, 0, 0, 0}, a3 = {0, 0, 0, 0};
    int i = b;
    for (; i + 3 < e; i += 4) {
        int s0 = srcs[i], s1 = srcs[i + 1], s2 = srcs[i + 2], s3 = srcs[i + 3];
        float4 v0 = in[s0 * FF4 + j];
        float4 v1 = in[s1 * FF4 + j];
        float4 v2 = in[s2 * FF4 + j];
        float4 v3 = in[s3 * FF4 + j];
        f4add(a0, v0); f4add(a1, v1); f4add(a2, v2); f4add(a3, v3);
    }
    for (; i < e; i++) {
        float4 v = in[srcs[i] * FF4 + j];
        f4add(a0, v);
    }
    float deg = (float)__ldg(&cnt[r]) * invN;
    float4 m = m2s4[j];
    float4 o;
    o.x = a0.x + a1.x + a2.x + a3.x - deg * m.x;
    o.y = a0.y + a1.y + a2.y + a3.y - deg * m.y;
    o.z = a0.z + a1.z + a2.z + a3.z - deg * m.z;
    o.w = a0.w + a1.w + a2.w + a3.w - deg * m.w;
    out[r * FF4 + j] = o;
}

// ================= tensor-core split-bf16 GEMM machinery =================
#define TPITCH 12

__device__ __forceinline__ void split2(float x0, float x1, unsigned& hi, unsigned& lo) {
    __nv_bfloat16 h0 = __float2bfloat16(x0);
    __nv_bfloat16 h1 = __float2bfloat16(x1);
    __nv_bfloat16 l0 = __float2bfloat16(x0 - __bfloat162float(h0));
    __nv_bfloat16 l1 = __float2bfloat16(x1 - __bfloat162float(h1));
    hi = ((unsigned)__bfloat16_as_ushort(h1) << 16) | (unsigned)__bfloat16_as_ushort(h0);
    lo = ((unsigned)__bfloat16_as_ushort(l1) << 16) | (unsigned)__bfloat16_as_ushort(l0);
}

__device__ __forceinline__ void mma16816(float* c, const unsigned* a, const unsigned* b) {
    asm volatile(
        "mma.sync.aligned.m16n8k16.row.col.f32.bf16.bf16.f32 "
        "{%0,%1,%2,%3}, {%4,%5,%6,%7}, {%8,%9}, {%0,%1,%2,%3};\n"
        : "+f"(c[0]), "+f"(c[1]), "+f"(c[2]), "+f"(c[3])
        : "r"(a[0]), "r"(a[1]), "r"(a[2]), "r"(a[3]), "r"(b[0]), "r"(b[1]));
}

__device__ __forceinline__ void mma_compute(
    const unsigned* __restrict__ AsHi, const unsigned* __restrict__ AsLo,
    const unsigned* __restrict__ BsHi, const unsigned* __restrict__ BsLo,
    float c[4][4][4], int wid, int lane) {
    int wm = (wid >> 2) * 64;
    int wn = (wid & 3) * 32;
    int g = lane >> 2, q = lane & 3;
    unsigned ahi[4][4], alo[4][4];
#pragma unroll
    for (int i = 0; i < 4; i++) {
        int r0 = (wm + i * 16 + g) * TPITCH;
        int r1 = r0 + 8 * TPITCH;
        ahi[i][0] = AsHi[r0 + q];     ahi[i][1] = AsHi[r1 + q];
        ahi[i][2] = AsHi[r0 + 4 + q]; ahi[i][3] = AsHi[r1 + 4 + q];
        alo[i][0] = AsLo[r0 + q];     alo[i][1] = AsLo[r1 + q];
        alo[i][2] = AsLo[r0 + 4 + q]; alo[i][3] = AsLo[r1 + 4 + q];
    }
#pragma unroll
    for (int j = 0; j < 4; j++) {
        int nb = (wn + j * 8 + g) * TPITCH;
        unsigned bh[2], bl[2];
        bh[0] = BsHi[nb + q]; bh[1] = BsHi[nb + 4 + q];
        bl[0] = BsLo[nb + q]; bl[1] = BsLo[nb + 4 + q];
#pragma unroll
        for (int i = 0; i < 4; i++) {
            mma16816(c[i][j], ahi[i], bh);
            mma16816(c[i][j], ahi[i], bl);
            mma16816(c[i][j], alo[i], bh);
        }
    }
}

// ---------------- C[FFxFF] += A^T * B over K rows (tensor core, split-K) ----------------
__global__ __launch_bounds__(256) void atgemm_tc_kernel(
    const float* __restrict__ A, const float* __restrict__ B,
    float* __restrict__ C, int Ktot, int KC) {
    __shared__ unsigned AsHi[128 * TPITCH], AsLo[128 * TPITCH];
    __shared__ unsigned BsHi[128 * TPITCH], BsLo[128 * TPITCH];
    int t = threadIdx.x;
    int bm = blockIdx.x * 128, bn = blockIdx.y * 128;
    int k0base = blockIdx.z * KC;
    int kend = k0base + KC; if (kend > Ktot) kend = Ktot;
    int wid = t >> 5, lane = t & 31;
    float c[4][4][4];
#pragma unroll
    for (int i = 0; i < 4; i++)
#pragma unroll
        for (int j = 0; j < 4; j++)
#pragma unroll
            for (int v = 0; v < 4; v++) c[i][j][v] = 0.f;

    int m = t & 127;
    int khalf = t >> 7;

    for (int k0 = k0base; k0 < k0base + KC; k0 += 16) {
        float xa[8], xb[8];
#pragma unroll
        for (int s = 0; s < 8; s++) {
            int kr = k0 + khalf * 8 + s;
            bool ok = kr < kend;
            xa[s] = ok ? A[(long)kr * FF + bm + m] : 0.f;
            xb[s] = ok ? B[(long)kr * FF + bn + m] : 0.f;
        }
        __syncthreads();
#pragma unroll
        for (int s = 0; s < 8; s += 2) {
            unsigned hi, lo;
            int w = m * TPITCH + khalf * 4 + s / 2;
            split2(xa[s], xa[s + 1], hi, lo);
            AsHi[w] = hi; AsLo[w] = lo;
            split2(xb[s], xb[s + 1], hi, lo);
            BsHi[w] = hi; BsLo[w] = lo;
        }
        __syncthreads();
        mma_compute(AsHi, AsLo, BsHi, BsLo, c, wid, lane);
    }

    int g = lane >> 2, q = lane & 3;
    int wm = bm + (wid >> 2) * 64;
    int wn = bn + (wid & 3) * 32;
#pragma unroll
    for (int i = 0; i < 4; i++) {
#pragma unroll
        for (int j = 0; j < 4; j++) {
            int col = wn + j * 8 + q * 2;
            int row0 = wm + i * 16 + g;
            int row1 = row0 + 8;
            atomicAdd(&C[(long)row0 * FF + col], c[i][j][0]);
            atomicAdd(&C[(long)row0 * FF + col + 1], c[i][j][1]);
            atomicAdd(&C[(long)row1 * FF + col], c[i][j][2]);
            atomicAdd(&C[(long)row1 * FF + col + 1], c[i][j][3]);
        }
    }
}

// ---------------- column reductions ----------------
__global__ void colsum_kernel(const float* __restrict__ X, float* __restrict__ a, int M) {
    int j = threadIdx.x;
    int r0 = blockIdx.x * 256;
    int r1 = r0 + 256; if (r1 > M) r1 = M;
    float s = 0.f;
    for (int r = r0; r < r1; r++) s += X[r * FF + j];
    atomicAdd(&a[j], s);
}

// colw3: a[j]+=sum X[r,j]*wA[r]; b[j]+=sum X[r,j]*wB[r]; c[j]+=sum X[r,j]
__global__ void colw3_kernel(const float* __restrict__ X, const float* __restrict__ wA,
                             const float* __restrict__ wB, float* __restrict__ a,
                             float* __restrict__ b, float* __restrict__ c, int M) {
    int j = threadIdx.x;
    int r0 = blockIdx.x * 256;
    int r1 = r0 + 256; if (r1 > M) r1 = M;
    float sa = 0.f, sb = 0.f, sc = 0.f;
    for (int r = r0; r < r1; r++) {
        float v = X[r * FF + j];
        sa += v * wA[r];
        sb += v * wB[r];
        sc += v;
    }
    atomicAdd(&a[j], sa);
    atomicAdd(&b[j], sb);
    atomicAdd(&c[j], sc);
}

// 8 scalar reductions over the degree vectors
__global__ void dots8_kernel(const float* __restrict__ e2a, const float* __restrict__ e4a,
                             const float* __restrict__ e2b, const float* __restrict__ e4b,
                             float* __restrict__ scal, int n) {
    int gid = blockIdx.x * blockDim.x + threadIdx.x;
    int stride = gridDim.x * blockDim.x;
    float s[8] = {0, 0, 0, 0, 0, 0, 0, 0};
    for (int i = gid; i < n; i += stride) {
        float x2 = e2a[i], x4 = e4a[i], y2 = e2b[i], y4 = e4b[i];
        s[0] += x4 * y4;
        s[1] += x4 * y2;
        s[2] += x4;
        s[3] += x2 * y4;
        s[4] += x2 * y2;
        s[5] += x2;
        s[6] += y4;
        s[7] += y2;
    }
#pragma unroll
    for (int k = 0; k < 8; k++)
        for (int o = 16; o; o >>= 1) s[k] += __shfl_xor_sync(0xffffffffu, s[k], o);
    if ((threadIdx.x & 31) == 0)
#pragma unroll
        for (int k = 0; k < 8; k++) atomicAdd(&scal[k], s[k]);
}

// ---------------- small 256x256x256 GEMMs ----------------
__global__ void mm256_nn_kernel(const float* __restrict__ A, const float* __restrict__ B,
                                float* __restrict__ C) {
    __shared__ float As[16][16];
    __shared__ float Bs[16][17];
    int tx = threadIdx.x, ty = threadIdx.y;
    int row = blockIdx.y * 16 + ty;
    int col = blockIdx.x * 16 + tx;
    float acc = 0.f;
    for (int k0 = 0; k0 < FF; k0 += 16) {
        As[ty][tx] = A[row * FF + k0 + tx];
        Bs[ty][tx] = B[(k0 + ty) * FF + col];
        __syncthreads();
#pragma unroll
        for (int kk = 0; kk < 16; kk++) acc += As[ty][kk] * Bs[kk][tx];
        __syncthreads();
    }
    C[row * FF + col] = acc;
}

__global__ void mm256_nt_kernel(const float* __restrict__ A, const float* __restrict__ B,
                                float* __restrict__ C) {
    __shared__ float As[16][16];
    __shared__ float Bs[16][17];
    int tx = threadIdx.x, ty = threadIdx.y;
    int row = blockIdx.y * 16 + ty;
    int col = blockIdx.x * 16 + tx;
    float acc = 0.f;
    for (int k0 = 0; k0 < FF; k0 += 16) {
        As[ty][tx] = A[row * FF + k0 + tx];
        Bs[ty][tx] = B[(blockIdx.x * 16 + tx) * FF + k0 + ty];  // B[col][k]
        __syncthreads();
#pragma unroll
        for (int kk = 0; kk < 16; kk++) acc += As[ty][kk] * Bs[kk][tx];
        __syncthreads();
    }
    C[row * FF + col] = acc;
}

__global__ void matvec256_kernel(const float* __restrict__ Mm, const float* __restrict__ x,
                                 float* __restrict__ y) {
    int r = blockIdx.x;
    int lane = threadIdx.x;
    float a = 0.f;
    for (int k = lane; k < FF; k += 32) a += Mm[r * FF + k] * x[k];
    for (int o = 16; o; o >>= 1) a += __shfl_xor_sync(0xffffffffu, a, o);
    if (lane == 0) y[r] = a;
}

// ---------------- BN-derived params: s (per branch) ----------------
// var_j = (W1_j . Graw . W1_j)/N - w_j^2 ;  w_j = (W1 m2s)_j / N
// s_j = gamma_j * rsqrt(var_j + eps)
__global__ void bnstats_kernel(const float* __restrict__ R1, const float* __restrict__ W1,
                               const float* __restrict__ m2s, const float* __restrict__ gamma,
                               float* __restrict__ s) {
    int j = blockIdx.x;
    int t = threadIdx.x;  // 256 threads
    __shared__ float sh1[256], sh2[256];
    float a1 = R1[j * FF + t] * W1[j * FF + t];
    float a2 = W1[j * FF + t] * m2s[t];
    sh1[t] = a1; sh2[t] = a2;
    __syncthreads();
    for (int o = 128; o; o >>= 1) {
        if (t < o) { sh1[t] += sh1[t + o]; sh2[t] += sh2[t + o]; }
        __syncthreads();
    }
    if (t == 0) {
        float invN = 1.0f / (float)NN;
        float w = sh2[0] * invN;
        float var = sh1[0] * invN - w * w;
        s[j] = gamma[j] * rsqrtf(var + 1e-5f);
    }
}

// W1s[k][j] = s[k] * W1[k][j]  (row-scale)
__global__ void rowscale_kernel(const float* __restrict__ W1, const float* __restrict__ s,
                                float* __restrict__ W1s) {
    int k = blockIdx.x, j = threadIdx.x;
    W1s[k * FF + j] = s[k] * W1[k * FF + j];
}

// ---------------- final assembly ----------------
__global__ void combine_kernel(const float* ga1, const float* gb1, const float* gc1,
                               const float* v1, const float* u, const float* b3,
                               const float* scal, float* Av, float* Bv, float* Cv) {
    int i = threadIdx.x;
    Av[i] = ga1[i] + scal[0] * v1[i] + scal[3] * u[i] + scal[6] * b3[i];
    Bv[i] = gb1[i] + scal[1] * v1[i] + scal[4] * u[i] + scal[7] * b3[i];
    Cv[i] = gc1[i] + scal[2] * v1[i] + scal[5] * u[i] + (float)NN * b3[i];
}

__global__ void assemble_kernel(const float* __restrict__ R, const float* __restrict__ Av,
                                const float* __restrict__ Bv, const float* __restrict__ Cv,
                                const float* __restrict__ v1, const float* __restrict__ u,
                                const float* __restrict__ b3, const float* __restrict__ v2,
                                const float* __restrict__ ha2, const float* __restrict__ hb2,
                                const float* __restrict__ hc2, float* __restrict__ out) {
    int i = blockIdx.x, j = threadIdx.x;
    out[i * FF + j] = R[i * FF + j]
                    + Av[i] * v2[j] + Bv[i] * u[j] + Cv[i] * b3[j]
                    + v1[i] * ha2[j] + u[i] * hb2[j] + b3[i] * hc2[j];
}

// ---------------- host ----------------
extern "C" void kernel_launch(void* const* d_in, const int* in_sizes, int n_in,
                              void* d_out, int out_size) {
    (void)in_sizes; (void)n_in; (void)out_size;
    const float* feature = (const float*)d_in[0];
    const int* src1 = (const int*)d_in[1];
    const int* dst1 = (const int*)d_in[2];
    const int* src2 = (const int*)d_in[3];
    const int* dst2 = (const int*)d_in[4];
    const float* W1 = (const float*)d_in[5];
    const float* b1 = (const float*)d_in[6];   // b1 cancels analytically in BN
    const float* W2 = (const float*)d_in[7];
    const float* b2 = (const float*)d_in[8];
    const float* W3 = (const float*)d_in[9];
    const float* b3 = (const float*)d_in[10];
    const float* gamma = (const float*)d_in[11];
    const float* beta = (const float*)d_in[12];
    (void)b1;
    float* out = (float*)d_out;

    float *T0, *T1, *Q1, *G, *W23, *Tm, *R, *C, *R1, *K1, *K2, *W1s;
    float *e2a, *e2b, *e4a, *e4b, *tmpv;
    float *m2s, *s, *u, *v1, *v2;
    float *p1a, *p1b, *p1c, *p2a, *p2b, *p2c;
    float *ga1, *gb1, *gc1, *ha2, *hb2, *hc2, *Av, *Bv, *Cv, *scal;
    int *cnt, *rowptr, *cursor, *csrsrc, *bsum, *boff;
    cudaGetSymbolAddress((void**)&T0, g_T0);
    cudaGetSymbolAddress((void**)&T1, g_T1);
    cudaGetSymbolAddress((void**)&Q1, g_Q1buf);
    cudaGetSymbolAddress((void**)&cnt, g_cnt);
    cudaGetSymbolAddress((void**)&rowptr, g_rowptr);
    cudaGetSymbolAddress((void**)&cursor, g_cursor);
    cudaGetSymbolAddress((void**)&csrsrc, g_csrsrc);
    cudaGetSymbolAddress((void**)&bsum, g_bsum);
    cudaGetSymbolAddress((void**)&boff, g_boff);
    cudaGetSymbolAddress((void**)&e2a, g_e2a);
    cudaGetSymbolAddress((void**)&e2b, g_e2b);
    cudaGetSymbolAddress((void**)&e4a, g_e4a);
    cudaGetSymbolAddress((void**)&e4b, g_e4b);
    cudaGetSymbolAddress((void**)&tmpv, g_tmpv);
    cudaGetSymbolAddress((void**)&G, g_G);
    cudaGetSymbolAddress((void**)&W23, g_W23);
    cudaGetSymbolAddress((void**)&Tm, g_Tm);
    cudaGetSymbolAddress((void**)&R, g_R);
    cudaGetSymbolAddress((void**)&C, g_C);
    cudaGetSymbolAddress((void**)&R1, g_R1);
    cudaGetSymbolAddress((void**)&K1, g_K1);
    cudaGetSymbolAddress((void**)&K2, g_K2);
    cudaGetSymbolAddress((void**)&W1s, g_W1s);
    cudaGetSymbolAddress((void**)&m2s, g_m2s);
    cudaGetSymbolAddress((void**)&s, g_s);
    cudaGetSymbolAddress((void**)&u, g_u);
    cudaGetSymbolAddress((void**)&v1, g_v1);
    cudaGetSymbolAddress((void**)&v2, g_v2);
    cudaGetSymbolAddress((void**)&p1a, g_p1a);
    cudaGetSymbolAddress((void**)&p1b, g_p1b);
    cudaGetSymbolAddress((void**)&p1c, g_p1c);
    cudaGetSymbolAddress((void**)&p2a, g_p2a);
    cudaGetSymbolAddress((void**)&p2b, g_p2b);
    cudaGetSymbolAddress((void**)&p2c, g_p2c);
    cudaGetSymbolAddress((void**)&ga1, g_ga1);
    cudaGetSymbolAddress((void**)&gb1, g_gb1);
    cudaGetSymbolAddress((void**)&gc1, g_gc1);
    cudaGetSymbolAddress((void**)&ha2, g_ha2);
    cudaGetSymbolAddress((void**)&hb2, g_hb2);
    cudaGetSymbolAddress((void**)&hc2, g_hc2);
    cudaGetSymbolAddress((void**)&Av, g_Av);
    cudaGetSymbolAddress((void**)&Bv, g_Bv);
    cudaGetSymbolAddress((void**)&Cv, g_Cv);
    cudaGetSymbolAddress((void**)&scal, g_scal);

    const int EG = (EE + 255) / 256;   // 3125
    const int NG = (NN + 255) / 256;   // 196
    const int SB = (NN + 1023) / 1024; // 49
    dim3 mmGrid(16, 16), mmBlk(16, 16);
    const float invN = 1.0f / (float)NN;

    // graph-independent precompute
    mm256_nn_kernel<<<mmGrid, mmBlk>>>(W3, W2, W23);    // W23 = W3*W2
    matvec256_kernel<<<FF, 32>>>(W3, b2, u);            // u = W3*b2
    // v' = W23*beta (the centered formulation makes the mean part cancel exactly)
    matvec256_kernel<<<FF, 32>>>(W23, beta, v1);
    matvec256_kernel<<<FF, 32>>>(W23, beta, v2);

    for (int br = 0; br < 2; br++) {
        const int* src = br ? src2 : src1;
        const int* dst = br ? dst2 : dst1;
        float* e2 = br ? e2b : e2a;
        float* e4 = br ? e4b : e4a;
        float* Kbr = br ? K2 : K1;

        // CSR build
        zero_i_kernel<<<NG, 256>>>(cnt, NN);
        hist_kernel<<<EG, 256>>>(dst, cnt, EE);
        scan1_kernel<<<SB, 1024>>>(cnt, bsum);
        scan2_kernel<<<1, 64>>>(bsum, boff, rowptr, SB);
        scan3_kernel<<<SB, 1024>>>(cnt, boff, rowptr, cursor);
        scatter_kernel<<<EG, 256>>>(src, dst, cursor, csrsrc, EE);

        // degree chain: e2 = A^2 1, e4 = A^4 1
        degsum_kernel<<<NG, 256>>>(rowptr, csrsrc, cnt, e2, NN);
        vec_agg_kernel<<<NG, 256>>>(e2, tmpv, rowptr, csrsrc, NN);
        vec_agg_kernel<<<NG, 256>>>(tmpv, e4, rowptr, csrsrc, NN);

        // P2 = A^2 f
        agg_kernel<<<NN, 64>>>((const float4*)feature, (float4*)T0, rowptr, csrsrc);
        agg_kernel<<<NN, 64>>>((const float4*)T0, (float4*)T1, rowptr, csrsrc);

        // BN statistics from P2: m2s = colsum(P2), Graw = P2^T P2
        zero_f_kernel<<<1, 256>>>(m2s, FF);
        colsum_kernel<<<NG, 256>>>(T1, m2s, NN);
        zero_f_kernel<<<FF, 256>>>(C, FF * FF);
        atgemm_tc_kernel<<<dim3(2, 2, 64), 256>>>(T1, T1, C, NN, 784);
        mm256_nn_kernel<<<mmGrid, mmBlk>>>(W1, C, R1);          // R1 = W1*Graw
        bnstats_kernel<<<FF, 256>>>(R1, W1, m2s, gamma, s);
        rowscale_kernel<<<FF, FF>>>(W1, s, W1s);                // W1s = diag(s)*W1
        mm256_nn_kernel<<<mmGrid, mmBlk>>>(W23, W1s, Kbr);      // K = W23*diag(s)*W1

        // P6c = A^4 (P2 - 1*mbar^T): center on the first hop (free via cnt[r]*mbar)
        agg_center_kernel<<<NN, 64>>>((const float4*)T1, (float4*)T0, rowptr, csrsrc,
                                      cnt, (const float4*)m2s, invN);
        agg_kernel<<<NN, 64>>>((const float4*)T0, (float4*)T1, rowptr, csrsrc);
        agg_kernel<<<NN, 64>>>((const float4*)T1, (float4*)T0, rowptr, csrsrc);
        agg_kernel<<<NN, 64>>>((const float4*)T0, (float4*)(br ? T1 : Q1), rowptr, csrsrc);
        // branch 0: P6c_1 in Q1buf;  branch 1: P6c_2 in T1
    }

    // G = P6c_1^T P6c_2
    zero_f_kernel<<<FF, 256>>>(G, FF * FF);
    atgemm_tc_kernel<<<dim3(2, 2, 64), 256>>>(Q1, T1, G, NN, 784);

    // cross vectors: p1* = P6c_1^T {e4_2, e2_2, 1}, p2* = P6c_2^T {e4_1, e2_1, 1}
    zero_f_kernel<<<1, 256>>>(p1a, FF);
    zero_f_kernel<<<1, 256>>>(p1b, FF);
    zero_f_kernel<<<1, 256>>>(p1c, FF);
    zero_f_kernel<<<1, 256>>>(p2a, FF);
    zero_f_kernel<<<1, 256>>>(p2b, FF);
    zero_f_kernel<<<1, 256>>>(p2c, FF);
    colw3_kernel<<<NG, 256>>>(Q1, e4b, e2b, p1a, p1b, p1c, NN);
    colw3_kernel<<<NG, 256>>>(T1, e4a, e2a, p2a, p2b, p2c, NN);

    // scalar dots
    zero_f_kernel<<<1, 8>>>(scal, 8);
    dots8_kernel<<<98, 256>>>(e2a, e4a, e2b, e4b, scal, NN);

    // rank-1 transforms
    matvec256_kernel<<<FF, 32>>>(K1, p1a, ga1);
    matvec256_kernel<<<FF, 32>>>(K1, p1b, gb1);
    matvec256_kernel<<<FF, 32>>>(K1, p1c, gc1);
    matvec256_kernel<<<FF, 32>>>(K2, p2a, ha2);
    matvec256_kernel<<<FF, 32>>>(K2, p2b, hb2);
    matvec256_kernel<<<FF, 32>>>(K2, p2c, hc2);
    combine_kernel<<<1, 256>>>(ga1, gb1, gc1, v1, u, b3, scal, Av, Bv, Cv);

    // core = K1 * G * K2^T
    mm256_nn_kernel<<<mmGrid, mmBlk>>>(K1, G, Tm);
    mm256_nt_kernel<<<mmGrid, mmBlk>>>(Tm, K2, R);

    assemble_kernel<<<FF, FF>>>(R, Av, Bv, Cv, v1, u, b3, v2, ha2, hb2, hc2, out);
}